// round 2
// baseline (speedup 1.0000x reference)
#include <cuda_runtime.h>
#include <math.h>

#define Bv   32
#define QL   32
#define DOCL 2048
#define Sv   64
#define Ev   300
#define Hv   256
#define G3   768   // 3*H

// ---------------- scratch (no allocations allowed) ----------------
__device__ float  g_facts[Bv*Sv*Ev];            // (B,S,E) sentence means
__device__ float  g_wT[3][Ev*G3];               // wih transposed: [e][g]
__device__ float4 g_whhP[3][(Hv/4)*G3];         // whh packed k-major: [k4][row] float4 over k
__device__ float  g_xg_q[Bv*QL*G3];
__device__ float  g_xg_f[Bv*Sv*G3];
__device__ float  g_xg_b[Bv*Sv*G3];
__device__ float  g_hf[Bv*Sv*Hv];
__device__ float  g_hb[Bv*Sv*Hv];

// packed 2xfp32 FMA (Blackwell f32x2 pipe, 2x FFMA throughput)
#define FFMA2(acc, a, b) asm("fma.rn.f32x2 %0, %1, %2, %0;" : "+l"(acc) : "l"(a), "l"(b))

__device__ __forceinline__ float psum2(unsigned long long v) {
    float lo, hi;
    asm("mov.b64 {%0,%1}, %2;" : "=f"(lo), "=f"(hi) : "l"(v));
    return lo + hi;
}

// ---------------- prep: pack whh k-major float4 ----------------
__global__ void pack_whh(const float* __restrict__ wq,
                         const float* __restrict__ wf,
                         const float* __restrict__ wb) {
    int idx = blockIdx.x * blockDim.x + threadIdx.x;
    const int per = (Hv/4) * G3;   // 49152
    if (idx >= 3 * per) return;
    int g = idx / per, rem = idx - g * per;
    int k4 = rem / G3, r = rem - k4 * G3;
    const float* w = (g == 0) ? wq : (g == 1) ? wf : wb;
    float4 v = *reinterpret_cast<const float4*>(w + (size_t)r * Hv + k4 * 4);
    g_whhP[g][k4 * G3 + r] = v;
}

// ---------------- prep: transpose wih -> [e][g] ----------------
__global__ void transpose_wih(const float* __restrict__ wq,
                              const float* __restrict__ wf,
                              const float* __restrict__ wb) {
    int idx = blockIdx.x * blockDim.x + threadIdx.x;
    const int per = Ev * G3;   // 230400
    if (idx >= 3 * per) return;
    int g = idx / per, rem = idx - g * per;
    int k = rem / G3, n = rem - k * G3;
    const float* w = (g == 0) ? wq : (g == 1) ? wf : wb;
    g_wT[g][(size_t)k * G3 + n] = w[(size_t)n * Ev + k];
}

// ---------------- facts: ragged per-sentence mean pooling ----------------
__global__ void facts_kernel(const int* __restrict__ docs,
                             const int* __restrict__ slen,
                             const float* __restrict__ emb) {
    __shared__ int toks[DOCL];
    int bs = blockIdx.x;
    int b = bs >> 6, s = bs & 63;
    const int* sl = slen + b * Sv;
    int start = 0;
    for (int i = 0; i < s; i++) start += sl[i];
    int len = sl[s];
    if (len > DOCL - start) len = DOCL - start;   // safety clamp
    const int* dp = docs + b * DOCL + start;
    for (int i = threadIdx.x; i < len; i += blockDim.x) toks[i] = dp[i];
    __syncthreads();
    int e = threadIdx.x;
    if (e < Ev) {
        float acc = 0.f;
        for (int i = 0; i < len; i++)
            acc += emb[(size_t)toks[i] * Ev + e];
        float d = (len > 0) ? (float)len : 1.0f;
        g_facts[(size_t)bs * Ev + e] = acc / d;
    }
}

// ---------------- xg GEMM: out[m][g] = sum_e A[m][e]*wih[g][e] + bih[g] ----------------
// which: 0 = question (A rows gathered from emb via tokens), 1 = fusion fwd (facts), 2 = fusion bwd (facts)
__global__ __launch_bounds__(256) void xg_gemm(int which,
                                               const int* __restrict__ tokens,
                                               const float* __restrict__ emb,
                                               const float* __restrict__ bih) {
    __shared__ float As[4][136];
    __shared__ float Bs[4][136];
    const float* wT = g_wT[which];
    float* out = (which == 0) ? g_xg_q : (which == 1) ? g_xg_f : g_xg_b;

    int tid = threadIdx.x;
    int m0 = blockIdx.y * 128, n0 = blockIdx.x * 128;
    int tx = tid & 15, ty = tid >> 4;

    float acc[8][8];
#pragma unroll
    for (int i = 0; i < 8; i++)
#pragma unroll
        for (int j = 0; j < 8; j++) acc[i][j] = 0.f;

    for (int k0 = 0; k0 < Ev; k0 += 4) {
#pragma unroll
        for (int i = 0; i < 2; i++) {
            int idx = tid + i * 256;
            int m = idx >> 2, k = idx & 3;
            const float* Arow = tokens ? (emb + (size_t)tokens[m0 + m] * Ev)
                                       : (g_facts + (size_t)(m0 + m) * Ev);
            As[k][m] = Arow[k0 + k];
            int n = idx & 127, kk = idx >> 7;
            Bs[kk][n] = wT[(size_t)(k0 + kk) * G3 + n0 + n];
        }
        __syncthreads();
#pragma unroll
        for (int k = 0; k < 4; k++) {
            float a[8], bb[8];
#pragma unroll
            for (int i = 0; i < 8; i++) a[i] = As[k][ty * 8 + i];
#pragma unroll
            for (int j = 0; j < 8; j++) bb[j] = Bs[k][tx * 8 + j];
#pragma unroll
            for (int i = 0; i < 8; i++)
#pragma unroll
                for (int j = 0; j < 8; j++) acc[i][j] = fmaf(a[i], bb[j], acc[i][j]);
        }
        __syncthreads();
    }
#pragma unroll
    for (int i = 0; i < 8; i++)
#pragma unroll
        for (int j = 0; j < 8; j++)
            out[(size_t)(m0 + ty * 8 + i) * G3 + n0 + tx * 8 + j] =
                acc[i][j] + bih[n0 + tx * 8 + j];
}

// ---------------- GRU recurrence: one CTA per (gru, batch) ----------------
// gru 0: question (T=32), 1: fusion fwd (T=64), 2: fusion bwd (T=64, reverse)
__global__ __launch_bounds__(256) void gru_kernel(const int* __restrict__ qlen,
                                                  const float* __restrict__ qbhh,
                                                  const float* __restrict__ fbhh,
                                                  const float* __restrict__ bbhh,
                                                  float* __restrict__ d_out) {
    __shared__ alignas(16) float shh[Hv];
    int id = blockIdx.x;
    int gru = id >> 5, b = id & 31;
    int tid = threadIdx.x;

    const float* bhh = (gru == 0) ? qbhh : (gru == 1) ? fbhh : bbhh;
    const float4* wP = g_whhP[gru];
    const float* xg = (gru == 0) ? (g_xg_q + (size_t)b * QL * G3)
                                 : (((gru == 1) ? g_xg_f : g_xg_b) + (size_t)b * Sv * G3);
    float* hout = (gru == 1) ? g_hf : g_hb;
    int T = (gru == 0) ? QL : Sv;

    shh[tid] = 0.f;
    float br = bhh[tid], bz = bhh[Hv + tid], bn = bhh[2 * Hv + tid];
    int qm1 = (gru == 0) ? (qlen[b] - 1) : -2;
    __syncthreads();

    for (int step = 0; step < T; step++) {
        int t = (gru == 2) ? (T - 1 - step) : step;

        unsigned long long ar0 = 0, ar1 = 0, az0 = 0, az1 = 0, an0 = 0, an1 = 0;
        const float4* wk = wP + tid;
        const ulonglong2* hp = reinterpret_cast<const ulonglong2*>(shh);
#pragma unroll 4
        for (int k4 = 0; k4 < Hv / 4; k4++) {
            ulonglong2 hv = hp[k4];
            ulonglong2 wr = *reinterpret_cast<const ulonglong2*>(wk);
            ulonglong2 wz = *reinterpret_cast<const ulonglong2*>(wk + Hv);
            ulonglong2 wn = *reinterpret_cast<const ulonglong2*>(wk + 2 * Hv);
            FFMA2(ar0, wr.x, hv.x); FFMA2(ar1, wr.y, hv.y);
            FFMA2(az0, wz.x, hv.x); FFMA2(az1, wz.y, hv.y);
            FFMA2(an0, wn.x, hv.x); FFMA2(an1, wn.y, hv.y);
            wk += G3;
        }
        float ghr = psum2(ar0) + psum2(ar1) + br;
        float ghz = psum2(az0) + psum2(az1) + bz;
        float ghn = psum2(an0) + psum2(an1) + bn;

        const float* xrow = xg + (size_t)t * G3;
        float r = 1.f / (1.f + expf(-(xrow[tid] + ghr)));
        float z = 1.f / (1.f + expf(-(xrow[Hv + tid] + ghz)));
        float n = tanhf(xrow[2 * Hv + tid] + r * ghn);
        float hold = shh[tid];
        float hnew = (1.f - z) * n + z * hold;

        __syncthreads();
        shh[tid] = hnew;
        __syncthreads();

        if (gru == 0) {
            if (t == qm1) d_out[(size_t)b * Hv + tid] = hnew;
        } else {
            hout[((size_t)b * Sv + t) * Hv + tid] = hnew;
        }
    }
}

// ---------------- combine: f_out = hf + hb, plus num_facts ----------------
__global__ void combine_kernel(const int* __restrict__ slen, float* __restrict__ d_out) {
    int idx = blockIdx.x * blockDim.x + threadIdx.x;
    const int NF = Bv * Sv * Hv;   // 524288
    if (idx < NF) d_out[Bv * Hv + idx] = g_hf[idx] + g_hb[idx];
    if (idx < Bv) {
        int c = 0;
        const int* sl = slen + idx * Sv;
        for (int s = 0; s < Sv; s++) c += (sl[s] > 0) ? 1 : 0;
        d_out[Bv * Hv + NF + idx] = (float)c;
    }
}

// ---------------- launch ----------------
extern "C" void kernel_launch(void* const* d_in, const int* in_sizes, int n_in,
                              void* d_out, int out_size) {
    const int*   queries = (const int*)d_in[0];
    const int*   qlen    = (const int*)d_in[1];
    const int*   docs    = (const int*)d_in[2];
    const int*   slen    = (const int*)d_in[3];
    const float* emb     = (const float*)d_in[4];
    const float* q_wih   = (const float*)d_in[5];
    const float* q_whh   = (const float*)d_in[6];
    const float* q_bih   = (const float*)d_in[7];
    const float* q_bhh   = (const float*)d_in[8];
    const float* f_wih   = (const float*)d_in[9];
    const float* f_whh   = (const float*)d_in[10];
    const float* f_bih   = (const float*)d_in[11];
    const float* f_bhh   = (const float*)d_in[12];
    const float* b_wih   = (const float*)d_in[13];
    const float* b_whh   = (const float*)d_in[14];
    const float* b_bih   = (const float*)d_in[15];
    const float* b_bhh   = (const float*)d_in[16];
    float* out = (float*)d_out;

    // prep
    pack_whh<<<(3 * (Hv/4) * G3 + 255) / 256, 256>>>(q_whh, f_whh, b_whh);
    transpose_wih<<<(3 * Ev * G3 + 255) / 256, 256>>>(q_wih, f_wih, b_wih);

    // facts
    facts_kernel<<<Bv * Sv, 320>>>(docs, slen, emb);

    // input projections
    dim3 gq(6, (Bv * QL) / 128);   // (6, 8)
    dim3 gf(6, (Bv * Sv) / 128);   // (6, 16)
    xg_gemm<<<gq, 256>>>(0, queries, emb, q_bih);
    xg_gemm<<<gf, 256>>>(1, nullptr, emb, f_bih);
    xg_gemm<<<gf, 256>>>(2, nullptr, emb, b_bih);

    // recurrence: 96 CTAs (3 GRUs x 32 batches)
    gru_kernel<<<96, 256>>>(qlen, q_bhh, f_bhh, b_bhh, out);

    // combine outputs
    combine_kernel<<<(Bv * Sv * Hv + 255) / 256, 256>>>(slen, out);
}

// round 3
// speedup vs baseline: 2.7684x; 2.7684x over previous
#include <cuda_runtime.h>
#include <math.h>
#include <stdint.h>

#define Bv   32
#define QL   32
#define DOCL 2048
#define Sv   64
#define Ev   300
#define Hv   256
#define G3   768    // 3*H
#define KP   304    // padded K for GEMM
#define MT   5120   // total GEMM rows (1024 q + 2048 f + 2048 b)
#define WSTR 268    // smem row stride (floats): 268 % 32 == 12 -> conflict-free
#define CLS  8      // cluster size

// ---------------- scratch ----------------
__device__ float g_facts[Bv*Sv*Ev];
__device__ float g_wTp[3][KP*G3];     // wih transposed+padded: [k][g]
__device__ float g_Ap[MT*KP];         // staged A (q emb rows + facts twice), k-padded
__device__ float g_xg_q[Bv*QL*G3];
__device__ float g_xg_f[Bv*Sv*G3];
__device__ float g_xg_b[Bv*Sv*G3];
__device__ float g_hf[Bv*Sv*Hv];
__device__ float g_hb[Bv*Sv*Hv];

// packed 2xfp32 FMA
#define FFMA2(acc, a, b) asm("fma.rn.f32x2 %0, %1, %2, %0;" : "+l"(acc) : "l"(a), "l"(b))
#define DUP2(d, s)       asm("mov.b64 %0, {%1, %1};" : "=l"(d) : "f"(s))

__device__ __forceinline__ float psum2(unsigned long long v) {
    float lo, hi;
    asm("mov.b64 {%0,%1}, %2;" : "=f"(lo), "=f"(hi) : "l"(v));
    return lo + hi;
}
__device__ __forceinline__ void unpack2(unsigned long long v, float& lo, float& hi) {
    asm("mov.b64 {%0,%1}, %2;" : "=f"(lo), "=f"(hi) : "l"(v));
}

// ---------------- prep: transpose wih -> [k][g], zero-pad k to 304 ----------------
__global__ void transpose_wih(const float* __restrict__ wq,
                              const float* __restrict__ wf,
                              const float* __restrict__ wb) {
    int idx = blockIdx.x * blockDim.x + threadIdx.x;
    const int per = KP * G3;
    if (idx >= 3 * per) return;
    int g = idx / per, rem = idx - g * per;
    int k = rem / G3, n = rem - k * G3;
    const float* w = (g == 0) ? wq : (g == 1) ? wf : wb;
    g_wTp[g][(size_t)k * G3 + n] = (k < Ev) ? w[(size_t)n * Ev + k] : 0.f;
}

// ---------------- facts: ragged per-sentence mean pooling ----------------
__global__ void facts_kernel(const int* __restrict__ docs,
                             const int* __restrict__ slen,
                             const float* __restrict__ emb) {
    __shared__ int toks[DOCL];
    int bs = blockIdx.x;
    int b = bs >> 6, s = bs & 63;
    const int* sl = slen + b * Sv;
    int start = 0;
    for (int i = 0; i < s; i++) start += sl[i];
    int len = sl[s];
    if (len > DOCL - start) len = DOCL - start;
    const int* dp = docs + b * DOCL + start;
    for (int i = threadIdx.x; i < len; i += blockDim.x) toks[i] = dp[i];
    __syncthreads();
    int e = threadIdx.x;
    if (e < Ev) {
        float acc = 0.f;
        for (int i = 0; i < len; i++)
            acc += emb[(size_t)toks[i] * Ev + e];
        float d = (len > 0) ? (float)len : 1.0f;
        g_facts[(size_t)bs * Ev + e] = acc / d;
    }
}

// ---------------- stage A: [5120][304] ----------------
__global__ void buildA(const int* __restrict__ queries,
                       const float* __restrict__ emb) {
    int idx = blockIdx.x * blockDim.x + threadIdx.x;   // float4 index
    const int C4 = KP / 4;                              // 76
    if (idx >= MT * C4) return;
    int m = idx / C4, c = idx - m * C4;
    float4 v = make_float4(0.f, 0.f, 0.f, 0.f);
    if (c < 75) {
        int k = c * 4;
        const float* src;
        if (m < 1024)      src = emb + (size_t)queries[m] * Ev;
        else if (m < 3072) src = g_facts + (size_t)(m - 1024) * Ev;
        else               src = g_facts + (size_t)(m - 3072) * Ev;
        v.x = src[k]; v.y = src[k+1]; v.z = src[k+2]; v.w = src[k+3];
    }
    *reinterpret_cast<float4*>(&g_Ap[(size_t)m * KP + c * 4]) = v;
}

// ---------------- merged xg GEMM: 5120 x 768 x 304, f32x2 inner ----------------
__global__ __launch_bounds__(256) void xg_gemm(const float* __restrict__ qbih,
                                               const float* __restrict__ fbih,
                                               const float* __restrict__ bbih) {
    __shared__ float As[16][132];
    __shared__ float Bs[16][132];
    int m0 = blockIdx.y * 128, n0 = blockIdx.x * 128;
    int which = (m0 < 1024) ? 0 : ((m0 < 3072) ? 1 : 2);
    const float* wT  = g_wTp[which];
    const float* bih = (which == 0) ? qbih : (which == 1) ? fbih : bbih;
    int mbase = (which == 0) ? 0 : (which == 1) ? 1024 : 3072;
    float* outb = ((which == 0) ? g_xg_q : (which == 1) ? g_xg_f : g_xg_b)
                  + (size_t)(m0 - mbase) * G3;

    int tid = threadIdx.x, tx = tid & 15, ty = tid >> 4;

    unsigned long long acc[8][4];
#pragma unroll
    for (int i = 0; i < 8; i++)
#pragma unroll
        for (int j = 0; j < 4; j++) acc[i][j] = 0ull;

    for (int k0 = 0; k0 < KP; k0 += 16) {
#pragma unroll
        for (int i = 0; i < 2; i++) {
            int idx = tid + i * 256;
            int r = idx >> 2, c = idx & 3;
            float4 av = *reinterpret_cast<const float4*>(
                &g_Ap[(size_t)(m0 + r) * KP + k0 + c * 4]);
            As[c*4+0][r] = av.x; As[c*4+1][r] = av.y;
            As[c*4+2][r] = av.z; As[c*4+3][r] = av.w;
            int kk = idx >> 5, nn = idx & 31;
            *reinterpret_cast<float4*>(&Bs[kk][nn * 4]) =
                *reinterpret_cast<const float4*>(&wT[(size_t)(k0 + kk) * G3 + n0 + nn * 4]);
        }
        __syncthreads();
#pragma unroll
        for (int k = 0; k < 16; k++) {
            float4 a0 = *reinterpret_cast<const float4*>(&As[k][ty * 8]);
            float4 a1 = *reinterpret_cast<const float4*>(&As[k][ty * 8 + 4]);
            ulonglong2 b01 = *reinterpret_cast<const ulonglong2*>(&Bs[k][tx * 8]);
            ulonglong2 b23 = *reinterpret_cast<const ulonglong2*>(&Bs[k][tx * 8 + 4]);
            float af[8] = {a0.x, a0.y, a0.z, a0.w, a1.x, a1.y, a1.z, a1.w};
#pragma unroll
            for (int i = 0; i < 8; i++) {
                unsigned long long ad; DUP2(ad, af[i]);
                FFMA2(acc[i][0], ad, b01.x);
                FFMA2(acc[i][1], ad, b01.y);
                FFMA2(acc[i][2], ad, b23.x);
                FFMA2(acc[i][3], ad, b23.y);
            }
        }
        __syncthreads();
    }
#pragma unroll
    for (int i = 0; i < 8; i++) {
        float* orow = outb + (size_t)(ty * 8 + i) * G3 + n0 + tx * 8;
#pragma unroll
        for (int jp = 0; jp < 4; jp++) {
            float lo, hi; unpack2(acc[i][jp], lo, hi);
            orow[2*jp]   = lo + bih[n0 + tx*8 + 2*jp];
            orow[2*jp+1] = hi + bih[n0 + tx*8 + 2*jp + 1];
        }
    }
}

// ---------------- GRU: 12 clusters x 8 CTAs, weights smem-resident ----------------
// cluster c: gru = c/4, batch-group = c%4 (8 batches). CTA rank owns 32 units.
extern "C" __global__ void __cluster_dims__(CLS, 1, 1) __launch_bounds__(256, 1)
gru_cluster(const int* __restrict__ qlen,
            const float* __restrict__ qwhh, const float* __restrict__ fwhh,
            const float* __restrict__ bwhh,
            const float* __restrict__ qbhh, const float* __restrict__ fbhh,
            const float* __restrict__ bbhh,
            float* __restrict__ d_out) {
    extern __shared__ float sm[];
    float* sw = sm;                    // [96][WSTR] weight rows (gate*32+u)
    float* sh = sm + 96 * WSTR;        // [2][8][WSTR] double-buffered h

    int cid = blockIdx.x / CLS;
    int crank = blockIdx.x - cid * CLS;
    int gru = cid >> 2, bg = cid & 3;
    int tid = threadIdx.x;

    const float* whh = (gru == 0) ? qwhh : (gru == 1) ? fwhh : bwhh;
    const float* bhh = (gru == 0) ? qbhh : (gru == 1) ? fbhh : bbhh;
    const float* xg  = (gru == 0) ? g_xg_q : (gru == 1) ? g_xg_f : g_xg_b;
    float* hout = (gru == 1) ? g_hf : g_hb;
    int T = (gru == 0) ? QL : Sv;

    // load 96 weight rows (3 gates x 32 units), coalesced float4
    for (int i = tid; i < 96 * 64; i += 256) {
        int gi = i >> 6, k4 = i & 63;
        int g = gi >> 5, u = gi & 31;
        float4 v = *reinterpret_cast<const float4*>(
            &whh[(size_t)((g << 8) + (crank << 5) + u) * Hv + (k4 << 2)]);
        *reinterpret_cast<float4*>(&sw[gi * WSTR + (k4 << 2)]) = v;
    }
    // zero h buffer 0
    for (int i = tid; i < 8 * WSTR; i += 256) sh[i] = 0.f;
    __syncthreads();
    asm volatile("barrier.cluster.arrive.aligned;" ::: "memory");
    asm volatile("barrier.cluster.wait.aligned;"   ::: "memory");

    int u  = tid >> 3, bl = tid & 7;
    int ug = (crank << 5) + u;       // global hidden unit
    int b  = (bg << 3) + bl;         // global batch
    float br = bhh[ug], bz = bhh[256 + ug], bn = bhh[512 + ug];
    int qm1 = (gru == 0) ? (qlen[b] - 1) : -2;
    const float* xgb = xg + (size_t)b * T * G3;

    const float* wr = sw + (size_t)(u)       * WSTR;
    const float* wz = sw + (size_t)(32 + u)  * WSTR;
    const float* wn = sw + (size_t)(64 + u)  * WSTR;

    uint32_t sh_u32;
    asm("{ .reg .u64 t; cvta.to.shared.u64 t, %1; cvt.u32.u64 %0, t; }"
        : "=r"(sh_u32) : "l"(sh));

    for (int step = 0; step < T; step++) {
        int t = (gru == 2) ? (T - 1 - step) : step;
        int p = step & 1;
        const float* hb = sh + (size_t)(p * 8 + bl) * WSTR;
        const float* xr = xgb + (size_t)t * G3;
        float ir = xr[ug], iz = xr[256 + ug], in_ = xr[512 + ug];

        unsigned long long ar0 = 0, ar1 = 0, az0 = 0, az1 = 0, an0 = 0, an1 = 0;
#pragma unroll 4
        for (int k4 = 0; k4 < 64; k4++) {
            ulonglong2 hv  = *reinterpret_cast<const ulonglong2*>(&hb[k4 << 2]);
            ulonglong2 wrv = *reinterpret_cast<const ulonglong2*>(&wr[k4 << 2]);
            ulonglong2 wzv = *reinterpret_cast<const ulonglong2*>(&wz[k4 << 2]);
            ulonglong2 wnv = *reinterpret_cast<const ulonglong2*>(&wn[k4 << 2]);
            FFMA2(ar0, wrv.x, hv.x); FFMA2(ar1, wrv.y, hv.y);
            FFMA2(az0, wzv.x, hv.x); FFMA2(az1, wzv.y, hv.y);
            FFMA2(an0, wnv.x, hv.x); FFMA2(an1, wnv.y, hv.y);
        }
        float ghr = psum2(ar0) + psum2(ar1) + br;
        float ghz = psum2(az0) + psum2(az1) + bz;
        float ghn = psum2(an0) + psum2(an1) + bn;

        float r = 1.f / (1.f + expf(-(ir + ghr)));
        float z = 1.f / (1.f + expf(-(iz + ghz)));
        float hold = sh[(size_t)(p * 8 + bl) * WSTR + ug];
        float n = tanhf(in_ + r * ghn);
        float hnew = (1.f - z) * n + z * hold;

        // broadcast hnew into buffer (1-p) of all 8 CTAs (incl. self)
        uint32_t loff = sh_u32 + (uint32_t)(((1 - p) * 8 + bl) * WSTR + ug) * 4u;
#pragma unroll
        for (int rk = 0; rk < CLS; rk++) {
            uint32_t raddr;
            asm("mapa.shared::cluster.u32 %0, %1, %2;" : "=r"(raddr) : "r"(loff), "r"(rk));
            asm volatile("st.shared::cluster.f32 [%0], %1;" :: "r"(raddr), "f"(hnew) : "memory");
        }
        asm volatile("barrier.cluster.arrive.aligned;" ::: "memory");
        // overlap gmem output with the cluster barrier
        if (gru == 0) {
            if (t == qm1) d_out[(size_t)b * Hv + ug] = hnew;
        } else {
            hout[((size_t)b * Sv + t) * Hv + ug] = hnew;
        }
        asm volatile("barrier.cluster.wait.aligned;" ::: "memory");
    }
}

// ---------------- combine: f_out = hf + hb, plus num_facts ----------------
__global__ void combine_kernel(const int* __restrict__ slen, float* __restrict__ d_out) {
    int idx = blockIdx.x * blockDim.x + threadIdx.x;
    const int NF = Bv * Sv * Hv;
    if (idx < NF) d_out[Bv * Hv + idx] = g_hf[idx] + g_hb[idx];
    if (idx < Bv) {
        int c = 0;
        const int* sl = slen + idx * Sv;
        for (int s = 0; s < Sv; s++) c += (sl[s] > 0) ? 1 : 0;
        d_out[Bv * Hv + NF + idx] = (float)c;
    }
}

// ---------------- launch ----------------
extern "C" void kernel_launch(void* const* d_in, const int* in_sizes, int n_in,
                              void* d_out, int out_size) {
    const int*   queries = (const int*)d_in[0];
    const int*   qlen    = (const int*)d_in[1];
    const int*   docs    = (const int*)d_in[2];
    const int*   slen    = (const int*)d_in[3];
    const float* emb     = (const float*)d_in[4];
    const float* q_wih   = (const float*)d_in[5];
    const float* q_whh   = (const float*)d_in[6];
    const float* q_bih   = (const float*)d_in[7];
    const float* q_bhh   = (const float*)d_in[8];
    const float* f_wih   = (const float*)d_in[9];
    const float* f_whh   = (const float*)d_in[10];
    const float* f_bih   = (const float*)d_in[11];
    const float* f_bhh   = (const float*)d_in[12];
    const float* b_wih   = (const float*)d_in[13];
    const float* b_whh   = (const float*)d_in[14];
    const float* b_bih   = (const float*)d_in[15];
    const float* b_bhh   = (const float*)d_in[16];
    float* out = (float*)d_out;

    const int GRU_SMEM = (96 * WSTR + 2 * 8 * WSTR) * 4;   // 120064 B
    cudaFuncSetAttribute(gru_cluster, cudaFuncAttributeMaxDynamicSharedMemorySize, GRU_SMEM);

    transpose_wih<<<(3 * KP * G3 + 255) / 256, 256>>>(q_wih, f_wih, b_wih);
    facts_kernel<<<Bv * Sv, 320>>>(docs, slen, emb);
    buildA<<<(MT * (KP / 4) + 255) / 256, 256>>>(queries, emb);

    dim3 gg(6, 40);
    xg_gemm<<<gg, 256>>>(q_bih, f_bih, b_bih);

    gru_cluster<<<96, 256, GRU_SMEM>>>(qlen, q_whh, f_whh, b_whh,
                                       q_bhh, f_bhh, b_bhh, out);

    combine_kernel<<<(Bv * Sv * Hv + 255) / 256, 256>>>(slen, out);
}